// round 4
// baseline (speedup 1.0000x reference)
#include <cuda_runtime.h>
#include <cuda_bf16.h>
#include <cstdint>

// YOLOv3 decode: x [16, 255, 76, 76] fp32 -> out [16, 3*5776, 85] fp32
// R4: persistent CTAs (grid=740) + double-buffered smem. TMA bulk store of
// tile i overlaps load of tile i+1; buffer reused at i+2 after
// cp.async.bulk.wait_group.read 1. R3 was latency-bound (no pipe >54%):
// per-CTA store-wait + 4368 block retires were exposed serialization.

#define YHW    5776
#define YC     85
#define HWT    64
#define YTPB   256
#define CHUNKS 91                  // ceil(5776/64); last = 16 hw
#define NTILES (48 * CHUNKS)       // 4368
#define NBLK   740                 // 148 SMs x 5 CTAs

__device__ __forceinline__ float ysig(float v) {
    return __fdividef(1.0f, 1.0f + __expf(-v));
}

template <bool TAIL>
__device__ __forceinline__ void load_tile(
    const float* __restrict__ xs, float* __restrict__ smb,
    int hw0, int nhw, float aw, float ah, int wid, int lane)
{
    #pragma unroll 3
    for (int u = wid; u < 44; u += 8) {
        const int g   = u >> 1;
        const int hwl = ((u & 1) << 5) + lane;      // 0..63
        if (TAIL && hwl >= nhw) continue;
        if (g < 21) {
            const int c0 = g * 4;
            const float* p = xs + (size_t)c0 * YHW + hwl;
            float v0 = p[0];
            float v1 = p[YHW];
            float v2 = p[2 * YHW];
            float v3 = p[3 * YHW];
            if (g == 0) {
                const unsigned hw = (unsigned)(hw0 + hwl);
                const unsigned hh = (hw * 55189u) >> 22;    // hw / 76
                const unsigned ww = hw - hh * 76u;
                v0 = (ysig(v0) + (float)ww) * (1.0f / 76.0f);
                v1 = (ysig(v1) + (float)hh) * (1.0f / 76.0f);
                v2 = __expf(v2) * aw;
                v3 = __expf(v3) * ah;
            } else {
                v0 = ysig(v0); v1 = ysig(v1);
                v2 = ysig(v2); v3 = ysig(v3);
            }
            float* d = smb + hwl * YC + c0;          // conflict-free STS.32
            d[0] = v0; d[1] = v1; d[2] = v2; d[3] = v3;
        } else {
            float v = xs[(size_t)84 * YHW + hwl];
            smb[hwl * YC + 84] = ysig(v);
        }
    }
}

__global__ __launch_bounds__(YTPB) void Yolo_59966333387037_kernel(
    const float* __restrict__ x,
    const float* __restrict__ anchors,
    float* __restrict__ out)
{
    __shared__ __align__(16) float sm[2][HWT * YC];   // 2 x 21760 B

    const int wid  = threadIdx.x >> 5;
    const int lane = threadIdx.x & 31;

    int it = 0;
    for (int tile = blockIdx.x; tile < NTILES; tile += NBLK, ++it) {
        const int s     = tile / CHUNKS;
        const int chunk = tile - s * CHUNKS;
        const int a     = s % 3;
        const float aw  = __ldg(anchors + 2 * a)     * (1.0f / 608.0f);
        const float ah  = __ldg(anchors + 2 * a + 1) * (1.0f / 608.0f);
        const int hw0   = chunk * HWT;
        const int nhw   = min(HWT, YHW - hw0);
        const float* xs = x + (size_t)s * YC * YHW + hw0;
        float* smb      = sm[it & 1];

        // Buffer reuse guard: store issued 2 iterations ago must have read smem.
        if (it >= 2 && threadIdx.x == 0)
            asm volatile("cp.async.bulk.wait_group.read 1;" ::: "memory");
        __syncthreads();

        if (nhw == HWT) load_tile<false>(xs, smb, hw0, nhw, aw, ah, wid, lane);
        else            load_tile<true >(xs, smb, hw0, nhw, aw, ah, wid, lane);
        __syncthreads();

        if (threadIdx.x == 0) {
            asm volatile("fence.proxy.async.shared::cta;" ::: "memory");
            uint32_t saddr;
            asm("{ .reg .u64 t; cvta.to.shared.u64 t, %1; cvt.u32.u64 %0, t; }"
                : "=r"(saddr) : "l"((const void*)smb));
            float* dst = out + ((size_t)s * YHW + hw0) * YC;
            const int bytes = nhw * YC * 4;          // 16B multiple
            asm volatile(
                "cp.async.bulk.global.shared::cta.bulk_group [%0], [%1], %2;"
                :: "l"(dst), "r"(saddr), "r"(bytes) : "memory");
            asm volatile("cp.async.bulk.commit_group;" ::: "memory");
        }
    }

    if (threadIdx.x == 0)
        asm volatile("cp.async.bulk.wait_group 0;" ::: "memory");
}

extern "C" void kernel_launch(void* const* d_in, const int* in_sizes, int n_in,
                              void* d_out, int out_size)
{
    const float* x       = (const float*)d_in[0];
    const float* anchors = (const float*)d_in[1];
    float* out           = (float*)d_out;

    Yolo_59966333387037_kernel<<<NBLK, YTPB>>>(x, anchors, out);
}

// round 9
// speedup vs baseline: 1.1031x; 1.1031x over previous
#include <cuda_runtime.h>
#include <cuda_bf16.h>
#include <cstdint>

// YOLOv3 decode: x [16, 255, 76, 76] fp32 -> out [16, 3*5776, 85] fp32
// R5 = R3 load phase (conflict-free STS, warp-uniform branches, 8 CTAs/SM)
//    + R4 pipelining (persistent CTAs, double buffer, async TMA store,
//      wait_group.read 1 before buffer reuse) WITHOUT the occupancy loss:
//      HWT=32 -> 2 x 10.88 KB smem = R3's footprint.
// R4 regressed because 44KB smem dropped occ to 58% (load-latency hiding lost
// more than store pipelining gained).

#define YHW    5776
#define YC     85
#define HWT    32
#define YTPB   256
#define CHUNKS 181                 // 180 full + 1 tail of 16
#define NTILES (48 * CHUNKS)       // 8688
#define NBLK   1184                // 148 SMs x 8 CTAs

__device__ __forceinline__ float ysig(float v) {
    return __fdividef(1.0f, 1.0f + __expf(-v));
}

template <bool TAIL>
__device__ __forceinline__ void load_tile(
    const float* __restrict__ xs, float* __restrict__ smb,
    int hw0, int nhw, float aw, float ah, int wid, int lane)
{
    // 22 warp-units: g = 0..20 c-quads, g = 21 is c==84. 32 hw per unit.
    #pragma unroll 3
    for (int g = wid; g < 22; g += 8) {
        const int hwl = lane;
        if (TAIL && hwl >= nhw) continue;
        if (g < 21) {
            const int c0 = g * 4;
            const float* p = xs + (size_t)c0 * YHW + hwl;
            float v0 = p[0];
            float v1 = p[YHW];
            float v2 = p[2 * YHW];
            float v3 = p[3 * YHW];
            if (g == 0) {
                const unsigned hw = (unsigned)(hw0 + hwl);
                const unsigned hh = (hw * 55189u) >> 22;    // hw / 76
                const unsigned ww = hw - hh * 76u;
                v0 = (ysig(v0) + (float)ww) * (1.0f / 76.0f);
                v1 = (ysig(v1) + (float)hh) * (1.0f / 76.0f);
                v2 = __expf(v2) * aw;
                v3 = __expf(v3) * ah;
            } else {
                v0 = ysig(v0); v1 = ysig(v1);
                v2 = ysig(v2); v3 = ysig(v3);
            }
            float* d = smb + hwl * YC + c0;     // lane delta 85 (odd): conflict-free
            d[0] = v0; d[1] = v1; d[2] = v2; d[3] = v3;
        } else {
            float v = xs[(size_t)84 * YHW + hwl];
            smb[hwl * YC + 84] = ysig(v);
        }
    }
}

__global__ __launch_bounds__(YTPB) void Yolo_59966333387037_kernel(
    const float* __restrict__ x,
    const float* __restrict__ anchors,
    float* __restrict__ out)
{
    __shared__ __align__(16) float sm[2][HWT * YC];   // 2 x 10880 B

    const int wid  = threadIdx.x >> 5;
    const int lane = threadIdx.x & 31;

    int it = 0;
    for (int tile = blockIdx.x; tile < NTILES; tile += NBLK, ++it) {
        const int s     = tile / CHUNKS;
        const int chunk = tile - s * CHUNKS;
        const int a     = s % 3;
        const float aw  = __ldg(anchors + 2 * a)     * (1.0f / 608.0f);
        const float ah  = __ldg(anchors + 2 * a + 1) * (1.0f / 608.0f);
        const int hw0   = chunk * HWT;
        const int nhw   = min(HWT, YHW - hw0);        // 32 or 16
        const float* xs = x + (size_t)s * YC * YHW + hw0;
        float* smb      = sm[it & 1];

        // Buffer reuse: the store issued 2 iterations ago must have READ smem.
        if (it >= 2 && threadIdx.x == 0)
            asm volatile("cp.async.bulk.wait_group.read 1;" ::: "memory");
        __syncthreads();

        if (nhw == HWT) load_tile<false>(xs, smb, hw0, nhw, aw, ah, wid, lane);
        else            load_tile<true >(xs, smb, hw0, nhw, aw, ah, wid, lane);
        __syncthreads();

        if (threadIdx.x == 0) {
            asm volatile("fence.proxy.async.shared::cta;" ::: "memory");
            uint32_t saddr;
            asm("{ .reg .u64 t; cvta.to.shared.u64 t, %1; cvt.u32.u64 %0, t; }"
                : "=r"(saddr) : "l"((const void*)smb));
            float* dst = out + ((size_t)s * YHW + hw0) * YC;
            const int bytes = nhw * YC * 4;           // 10880 or 5440
            asm volatile(
                "cp.async.bulk.global.shared::cta.bulk_group [%0], [%1], %2;"
                :: "l"(dst), "r"(saddr), "r"(bytes) : "memory");
            asm volatile("cp.async.bulk.commit_group;" ::: "memory");
        }
    }

    // Drain all outstanding bulk stores before grid completion.
    if (threadIdx.x == 0)
        asm volatile("cp.async.bulk.wait_group 0;" ::: "memory");
}

extern "C" void kernel_launch(void* const* d_in, const int* in_sizes, int n_in,
                              void* d_out, int out_size)
{
    const float* x       = (const float*)d_in[0];
    const float* anchors = (const float*)d_in[1];
    float* out           = (float*)d_out;

    Yolo_59966333387037_kernel<<<NBLK, YTPB>>>(x, anchors, out);
}

// round 10
// speedup vs baseline: 1.3067x; 1.1846x over previous
#include <cuda_runtime.h>
#include <cuda_bf16.h>
#include <cstdint>

// YOLOv3 decode: x [16, 255, 76, 76] fp32 -> out [16, 3*5776, 85] fp32
// R10: attack the load phase (invariant across R3/R5 at ~33us):
//  - LDG.64: lane holds hw pair (2l, 2l+1); 256B/warp-request, half the LDGs
//  - sigmoid = 0.5*tanh.approx(x/2)+0.5 : 1 MUFU instead of 2 (EX2+RCP)
//  - STS.64 on even-hw rows (parity-aligned); 2-way conflicts accepted
//  - HWT=64, single 21.76KB buffer -> 8 CTAs/SM (R4 proved occupancy rules)
//  - persistent CTAs; buffer reuse after cp.async.bulk.wait_group.read 0
//    (drains TMA smem-read side only, not gmem-write completion)

#define YHW    5776
#define YC     85
#define HWT    64
#define YTPB   256
#define CHUNKS 91                  // 90 full + tail of 16 hw
#define NTILES (48 * CHUNKS)       // 4368
#define NBLK   1184                // 148 x 8

__device__ __forceinline__ float ytanh(float x) {
    float r;
    asm("tanh.approx.f32 %0, %1;" : "=f"(r) : "f"(x));
    return r;
}
__device__ __forceinline__ float ysig(float v) {
    return fmaf(0.5f, ytanh(0.5f * v), 0.5f);     // 1 MUFU + 1 FMA
}

template <bool TAIL>
__device__ __forceinline__ void load_tile(
    const float* __restrict__ xs, float* __restrict__ smb,
    int hw0, int nhw, float aw, float ah, int wid, int lane)
{
    const int hwe = 2 * lane;                      // even hw within tile
    // 22 warp-units: g=0..20 channel quads, g=21 is c==84; 64 hw per unit.
    #pragma unroll 3
    for (int g = wid; g < 22; g += 8) {
        if (TAIL && hwe >= nhw) continue;
        if (g < 21) {
            const int c0 = g * 4;
            const float2* p = (const float2*)(xs + (size_t)c0 * YHW) + lane;
            float2 va = p[0];                      // channel c0
            float2 vb = p[YHW / 2];                // c0+1
            float2 vc = p[YHW];                    // c0+2
            float2 vd = p[3 * (YHW / 2)];          // c0+3
            if (g == 0) {
                const unsigned hw = (unsigned)(hw0 + hwe);      // even
                const unsigned hh = (hw * 55189u) >> 22;        // hw / 76
                const unsigned ww = hw - hh * 76u;              // even -> no wrap in pair
                const float fw = (float)ww, fh = (float)hh;
                va.x = (ysig(va.x) + fw)        * (1.0f / 76.0f);
                va.y = (ysig(va.y) + fw + 1.0f) * (1.0f / 76.0f);
                vb.x = (ysig(vb.x) + fh)        * (1.0f / 76.0f);
                vb.y = (ysig(vb.y) + fh)        * (1.0f / 76.0f);
                vc.x = __expf(vc.x) * aw;  vc.y = __expf(vc.y) * aw;
                vd.x = __expf(vd.x) * ah;  vd.y = __expf(vd.y) * ah;
            } else {
                va.x = ysig(va.x); va.y = ysig(va.y);
                vb.x = ysig(vb.x); vb.y = ysig(vb.y);
                vc.x = ysig(vc.x); vc.y = ysig(vc.y);
                vd.x = ysig(vd.x); vd.y = ysig(vd.y);
            }
            float* d = smb + (size_t)hwe * YC + c0;
            // even-hw row: element index 170*l + 4g is even -> 8B aligned
            *(float2*)(d)     = make_float2(va.x, vb.x);
            *(float2*)(d + 2) = make_float2(vc.x, vd.x);
            // odd-hw row (d+85): odd index -> scalar stores
            d[YC]     = va.y;
            d[YC + 1] = vb.y;
            d[YC + 2] = vc.y;
            d[YC + 3] = vd.y;
        } else {
            const float2* p = (const float2*)(xs + (size_t)84 * YHW) + lane;
            float2 v = p[0];
            float* d = smb + (size_t)hwe * YC + 84;
            d[0]  = ysig(v.x);
            d[YC] = ysig(v.y);
        }
    }
}

__global__ __launch_bounds__(YTPB) void Yolo_59966333387037_kernel(
    const float* __restrict__ x,
    const float* __restrict__ anchors,
    float* __restrict__ out)
{
    __shared__ __align__(16) float sm[HWT * YC];   // 21760 B, single buffer

    const int wid  = threadIdx.x >> 5;
    const int lane = threadIdx.x & 31;

    for (int tile = blockIdx.x; tile < NTILES; tile += NBLK) {
        const int s     = tile / CHUNKS;
        const int chunk = tile - s * CHUNKS;
        const int a     = s % 3;
        const float aw  = __ldg(anchors + 2 * a)     * (1.0f / 608.0f);
        const float ah  = __ldg(anchors + 2 * a + 1) * (1.0f / 608.0f);
        const int hw0   = chunk * HWT;
        const int nhw   = min(HWT, YHW - hw0);      // 64 or 16
        const float* xs = x + (size_t)s * YC * YHW + hw0;

        // Previous TMA store must have finished READING smem before overwrite.
        if (threadIdx.x == 0)
            asm volatile("cp.async.bulk.wait_group.read 0;" ::: "memory");
        __syncthreads();

        if (nhw == HWT) load_tile<false>(xs, sm, hw0, nhw, aw, ah, wid, lane);
        else            load_tile<true >(xs, sm, hw0, nhw, aw, ah, wid, lane);
        __syncthreads();

        if (threadIdx.x == 0) {
            asm volatile("fence.proxy.async.shared::cta;" ::: "memory");
            uint32_t saddr;
            asm("{ .reg .u64 t; cvta.to.shared.u64 t, %1; cvt.u32.u64 %0, t; }"
                : "=r"(saddr) : "l"((const void*)sm));
            float* dst = out + ((size_t)s * YHW + hw0) * YC;
            const int bytes = nhw * YC * 4;         // 21760 or 5440
            asm volatile(
                "cp.async.bulk.global.shared::cta.bulk_group [%0], [%1], %2;"
                :: "l"(dst), "r"(saddr), "r"(bytes) : "memory");
            asm volatile("cp.async.bulk.commit_group;" ::: "memory");
        }
    }

    if (threadIdx.x == 0)
        asm volatile("cp.async.bulk.wait_group 0;" ::: "memory");
}

extern "C" void kernel_launch(void* const* d_in, const int* in_sizes, int n_in,
                              void* d_out, int out_size)
{
    const float* x       = (const float*)d_in[0];
    const float* anchors = (const float*)d_in[1];
    float* out           = (float*)d_out;

    Yolo_59966333387037_kernel<<<NBLK, YTPB>>>(x, anchors, out);
}